// round 15
// baseline (speedup 1.0000x reference)
#include <cuda_runtime.h>
#include <math.h>
#include <stdint.h>

// ---------------------------------------------------------------------------
// GPT transformer block. GEMMs + flash on tf32 mma.sync (tcgen05 unavailable:
// harness ptxas targets sm_103 without the 'a' feature set).
// GEMM: 128x128 CTA tile, 2 CTAs/SM, BK=32, 3-stage cp.async, ldmatrix feeds.
// Flash: 64-row q-tile, 4 warps, double-buffered K (P overlays current K),
// V-load hidden behind S+softmax, ldmatrix feeds Q/K/P, longest-first order.
//   B=2, T=2048, C=1024, H=16, HD=64
// Output layout (float32): [ x (B*T*C) | att_entropy (1) | present (2*B*H*T*HD) ]
// present region starts at float offset XS+1 -> NOT 16B aligned (scalar only).
// ---------------------------------------------------------------------------

namespace {
constexpr int Bc = 2, Tc = 2048, Cc = 1024, Hc = 16, HDc = 64;
constexpr int Mrows = Bc * Tc;            // 4096
constexpr int XS    = Bc * Tc * Cc;       // 4194304
constexpr int PRES  = Bc * Hc * Tc * HDc; // 4194304

// flash smem strides (words) -- conflict-free fragment loads (mod 32 = 4/8)
constexpr int QS_ = 68, KS_ = 68, VS_ = 72;
// Q[64] + K0[64] + K1[64] + V[64] + H[64 words]  (P overlays current K buf)
constexpr int FLASH_SMEM = (64*QS_ + 2*64*KS_ + 64*VS_ + 64) * 4; // 70912 B

// cp.async GEMM: 128(M) x 128(N) CTA tile, BK=32, 3 stages, 2 CTAs/SM
constexpr int TSg   = 36;                  // row stride words (144B, 16B mult)
constexpr int STG   = 3;
constexpr int ATILE = 128 * TSg;           // words per operand per stage
constexpr int GEMM_SMEM = STG * 2 * ATILE * 4; // 110592 B

// fused weight-cvt sizes (float4 units)
constexpr int N4_A = 3 * Cc * Cc / 4;      // w_attn
constexpr int N4_P = Cc * Cc / 4;          // w_proj
constexpr int N4_F = Cc * Cc;              // w_fc  (4C*C/4)
constexpr int N4_M = Cc * Cc;              // w_mlp
constexpr int N4_ALL = N4_A + N4_P + N4_F + N4_M; // 3145728
}

// scratch (device globals -- no allocations allowed)
__device__ float g_h[Mrows * Cc];       // LN outputs / attention y (reused)
__device__ float g_q[PRES];             // Q tf32, pre-scaled 1/8 (B,H,T,HD)
__device__ float g_k[PRES];             // K tf32 (B,H,T,HD)
__device__ float g_v[PRES];             // V tf32 (B,H,T,HD)
__device__ float g_a[Mrows * 4 * Cc];   // FC activation (B,T,4C)
__device__ float g_wa[3 * Cc * Cc];     // tf32-rounded w_attn
__device__ float g_wp[Cc * Cc];         // tf32-rounded w_proj
__device__ float g_wf[4 * Cc * Cc];     // tf32-rounded w_fc
__device__ float g_wm[4 * Cc * Cc];     // tf32-rounded w_mlp

// ---------------------------------------------------------------------------
__device__ __forceinline__ uint32_t smem_u32(const void* p) {
    uint32_t a;
    asm("{ .reg .u64 t; cvta.to.shared.u64 t, %1; cvt.u32.u64 %0, t; }"
        : "=r"(a) : "l"(p));
    return a;
}
__device__ __forceinline__ void cp_async16(uint32_t dst, const void* src) {
    asm volatile("cp.async.cg.shared.global [%0], [%1], 16;"
                 :: "r"(dst), "l"(src));
}
#define CP_COMMIT() asm volatile("cp.async.commit_group;" ::: "memory")
#define CP_WAIT1()  asm volatile("cp.async.wait_group 1;"  ::: "memory")

__device__ __forceinline__ void ldsm_x4(unsigned* r, uint32_t addr) {
    asm volatile("ldmatrix.sync.aligned.m8n8.x4.shared.b16 {%0,%1,%2,%3}, [%4];"
                 : "=r"(r[0]), "=r"(r[1]), "=r"(r[2]), "=r"(r[3]) : "r"(addr));
}

__device__ __forceinline__ unsigned f2tf32(float f) {
    unsigned u;
    asm("cvt.rna.tf32.f32 %0, %1;" : "=r"(u) : "f"(f));
    return u;
}
__device__ __forceinline__ float tf32f(float f) {
    return __uint_as_float(f2tf32(f));
}
__device__ __forceinline__ void mma_tf32(float* c, const unsigned* a, const unsigned* b) {
    asm volatile(
        "mma.sync.aligned.m16n8k8.row.col.f32.tf32.tf32.f32 "
        "{%0,%1,%2,%3},{%4,%5,%6,%7},{%8,%9},{%0,%1,%2,%3};"
        : "+f"(c[0]), "+f"(c[1]), "+f"(c[2]), "+f"(c[3])
        : "r"(a[0]), "r"(a[1]), "r"(a[2]), "r"(a[3]), "r"(b[0]), "r"(b[1]));
}
__device__ __forceinline__ float gelu_f(float v) {
    const float c = 0.7978845608028654f;
    float u = c * (v + 0.044715f * v * v * v);
    return 0.5f * v * (1.0f + tanhf(u));
}
// fast exp on the FMA pipe (no MUFU). rel err ~4e-5.
__device__ __forceinline__ float fexp(float x) {
    x = fmaxf(x, -87.0f);
    float z = x * 1.442695041f;
    float t = z + 12582912.0f;
    float n = t - 12582912.0f;
    float r = z - n;
    float p = 9.61812910e-3f;
    p = fmaf(p, r, 5.55041087e-2f);
    p = fmaf(p, r, 2.40226507e-1f);
    p = fmaf(p, r, 6.93147182e-1f);
    p = fmaf(p, r, 1.0f);
    return __int_as_float(__float_as_int(p) + (__float_as_int(t) << 23));
}

// ---------------------------------------------------------------------------
// fused: zero entropy scalar + tf32-round all four weight matrices
__global__ void cvt_all_kernel(const float4* __restrict__ wa,
                               const float4* __restrict__ wp,
                               const float4* __restrict__ wf,
                               const float4* __restrict__ wm,
                               float4* __restrict__ oa,
                               float4* __restrict__ op,
                               float4* __restrict__ of,
                               float4* __restrict__ om,
                               float* __restrict__ ent)
{
    long i = (long)blockIdx.x * 256 + threadIdx.x;
    if (i == 0) *ent = 0.0f;
    if (i >= N4_ALL) return;
    const float4* src; float4* dst; long j = i;
    if (j < N4_A)            { src = wa; dst = oa; }
    else if ((j -= N4_A) < N4_P) { src = wp; dst = op; }
    else if ((j -= N4_P) < N4_F) { src = wf; dst = of; }
    else { j -= N4_F;          src = wm; dst = om; }
    float4 v = src[j];
    v.x = tf32f(v.x); v.y = tf32f(v.y);
    v.z = tf32f(v.z); v.w = tf32f(v.w);
    dst[j] = v;
}

// ---------------------------------------------------------------------------
// LayerNorm: one block per row, 256 threads, 1 float4/thread; tf32 output.
__global__ void ln_kernel(const float* __restrict__ x,
                          const float* __restrict__ w,
                          const float* __restrict__ b,
                          float* __restrict__ out)
{
    int row = blockIdx.x, tid = threadIdx.x;
    float4 v = ((const float4*)(x + (long)row * Cc))[tid];
    float s  = v.x + v.y + v.z + v.w;
    float s2 = v.x*v.x + v.y*v.y + v.z*v.z + v.w*v.w;
    __shared__ float rs[8], rs2[8];
    #pragma unroll
    for (int o = 16; o; o >>= 1) {
        s  += __shfl_xor_sync(0xffffffffu, s,  o);
        s2 += __shfl_xor_sync(0xffffffffu, s2, o);
    }
    int lane = tid & 31, wid = tid >> 5;
    if (lane == 0) { rs[wid] = s; rs2[wid] = s2; }
    __syncthreads();
    if (wid == 0) {
        s  = (lane < 8) ? rs[lane]  : 0.f;
        s2 = (lane < 8) ? rs2[lane] : 0.f;
        #pragma unroll
        for (int o = 4; o; o >>= 1) {
            s  += __shfl_xor_sync(0xffffffffu, s,  o);
            s2 += __shfl_xor_sync(0xffffffffu, s2, o);
        }
        if (lane == 0) { rs[0] = s; rs2[0] = s2; }
    }
    __syncthreads();
    float mean = rs[0] * (1.0f / Cc);
    float var  = rs2[0] * (1.0f / Cc) - mean * mean;
    float inv  = rsqrtf(var + 1e-5f);
    float4 w4 = ((const float4*)w)[tid];
    float4 b4 = ((const float4*)b)[tid];
    float4 o4;
    o4.x = tf32f((v.x - mean) * inv * w4.x + b4.x);
    o4.y = tf32f((v.y - mean) * inv * w4.y + b4.y);
    o4.z = tf32f((v.z - mean) * inv * w4.z + b4.z);
    o4.w = tf32f((v.w - mean) * inv * w4.w + b4.w);
    ((float4*)(out + (long)row * Cc))[tid] = o4;
}

// ---------------------------------------------------------------------------
// tf32 mma.sync GEMM (unchanged from R14).
template <int EPI>
__global__ __launch_bounds__(256, 2)
void gemm_cp_kernel(const float* __restrict__ A,
                    const float* __restrict__ W,
                    const float* __restrict__ bias,
                    const float* __restrict__ res,
                    float* __restrict__ outp,
                    float* __restrict__ out_k,
                    float* __restrict__ out_v,
                    float* __restrict__ pres_k,
                    float* __restrict__ pres_v,
                    int K, int N)
{
    extern __shared__ float sf[];
    float* sA = sf;                      // [STG][128][TSg]
    float* sB = sf + STG * ATILE;        // [STG][128][TSg]
    uint32_t sAu = smem_u32(sA), sBu = smem_u32(sB);

    int tid = threadIdx.x;
    int mbase = blockIdx.y * 128, nbase = blockIdx.x * 128;
    int wid = tid >> 5, lane = tid & 31;
    int g = lane >> 2, tig = lane & 3;
    int wm = wid >> 2, wn = wid & 3;     // 2 x 4 warp grid
    int moff = wm * 64, noff = wn * 32;
    int nst = K >> 5;

    float acc[4][4][4] = {};             // 64x32 per warp

    int aOff = (lane & 15) * TSg + ((lane >> 4) << 2);
    int bOff = ((lane & 7) + ((lane >> 4) << 3)) * TSg + (((lane >> 3) & 1) << 2);

    auto issueQ = [&](int st, int q) {
        if (st < nst) {
            int k0 = st << 5, buf = st % STG;
            int id = tid + (q << 8);
            int row = id >> 3, c4 = (id & 7) << 2;
            uint32_t off = ((buf * 128 + row) * TSg + c4) * 4;
            cp_async16(sAu + off, A + (long)(mbase + row) * K + k0 + c4);
            cp_async16(sBu + off, W + (long)(nbase + row) * K + k0 + c4);
        }
    };
    auto issueAll = [&](int st) {
        #pragma unroll
        for (int q = 0; q < 4; q++) issueQ(st, q);
        CP_COMMIT();
    };

    issueAll(0);
    issueAll(1);

    for (int it = 0; it < nst; it++) {
        CP_WAIT1();
        __syncthreads();

        uint32_t cAu = sAu + ((it % STG) * ATILE) * 4;
        uint32_t cBu = sBu + ((it % STG) * ATILE) * 4;
        #pragma unroll
        for (int x = 0; x < 4; x++) {
            issueQ(it + 2, x);
            int kk = x * 8;
            unsigned afr[4][4], bfr[2][4];
            #pragma unroll
            for (int mf = 0; mf < 4; mf++)
                ldsm_x4(afr[mf],
                        cAu + (((moff + mf * 16) * TSg) + kk + aOff) * 4);
            #pragma unroll
            for (int np = 0; np < 2; np++)
                ldsm_x4(bfr[np],
                        cBu + (((noff + np * 16) * TSg) + kk + bOff) * 4);
            #pragma unroll
            for (int mf = 0; mf < 4; mf++) {
                #pragma unroll
                for (int nf = 0; nf < 4; nf++)
                    mma_tf32(acc[mf][nf], afr[mf], bfr[nf >> 1] + ((nf & 1) << 1));
            }
        }
        CP_COMMIT();
    }

    if (EPI == 0) {
        int region = nbase >> 10;
        float* dst  = (region == 0) ? outp : (region == 1) ? out_k  : out_v;
        float* dst2 = (region == 0) ? (float*)0
                    : (region == 1) ? pres_k : pres_v;
        #pragma unroll
        for (int mf = 0; mf < 4; mf++) {
            #pragma unroll
            for (int i = 0; i < 2; i++) {
                int row = mbase + moff + mf * 16 + g + i * 8;
                int bidx = row >> 11;
                int t    = row & (Tc - 1);
                #pragma unroll
                for (int nf = 0; nf < 4; nf++) {
                    int n = nbase + noff + nf * 8 + tig * 2;
                    float2 v;
                    v.x = acc[mf][nf][i * 2 + 0] + bias[n];
                    v.y = acc[mf][nf][i * 2 + 1] + bias[n + 1];
                    int nl = n & (Cc - 1);
                    int head = nl >> 6, d = nl & 63;
                    long idx = (((long)(bidx * Hc + head) * Tc) + t) * HDc + d;
                    if (region == 0) {
                        *(float2*)(dst + idx) =
                            make_float2(tf32f(v.x * 0.125f), tf32f(v.y * 0.125f));
                    } else {
                        *(float2*)(dst + idx) =
                            make_float2(tf32f(v.x), tf32f(v.y));
                        dst2[idx] = v.x; dst2[idx + 1] = v.y;
                    }
                }
            }
        }
    } else {
        #pragma unroll
        for (int mf = 0; mf < 4; mf++) {
            #pragma unroll
            for (int i = 0; i < 2; i++) {
                int row = mbase + moff + mf * 16 + g + i * 8;
                #pragma unroll
                for (int nf = 0; nf < 4; nf++) {
                    int n = nbase + noff + nf * 8 + tig * 2;
                    long idx = (long)row * N + n;
                    float2 v;
                    v.x = acc[mf][nf][i * 2 + 0] + bias[n];
                    v.y = acc[mf][nf][i * 2 + 1] + bias[n + 1];
                    if (EPI == 1) {
                        float2 r2 = *(const float2*)(res + idx);
                        v.x += r2.x; v.y += r2.y;
                    } else {
                        v.x = tf32f(gelu_f(v.x));
                        v.y = tf32f(gelu_f(v.y));
                    }
                    *(float2*)(outp + idx) = v;
                }
            }
        }
    }
}

// ---------------------------------------------------------------------------
// Flash attention: 64-row q-tile, 4 warps x 16 rows, tf32 mma.sync.
// Software-pipelined: K double-buffered (prefetched one kt ahead), P overlays
// the current K buffer (K dead after S), V load hidden behind S+softmax.
// Commit order: [Q+K0] | V0, K1 | V1, K2 | ... ; every wait = wait_group 1.
__global__ __launch_bounds__(128, 3)
void flash_mma_kernel(const float* __restrict__ Q,
                      const float* __restrict__ Kp,
                      const float* __restrict__ Vp,
                      float* __restrict__ Y,
                      float* __restrict__ ent)
{
    extern __shared__ float sm[];
    float* Qs  = sm;                    // [64][QS_]
    float* Ks0 = Qs  + 64 * QS_;        // [64][KS_] parity 0 (P overlay)
    float* Ks1 = Ks0 + 64 * KS_;        // [64][KS_] parity 1 (P overlay)
    float* Vs  = Ks1 + 64 * KS_;        // [64][VS_]
    float* Hs  = Vs  + 64 * VS_;        // [64]
    uint32_t Qsu  = smem_u32(Qs);
    uint32_t Ks0u = smem_u32(Ks0), Ks1u = smem_u32(Ks1);
    uint32_t Vsu  = smem_u32(Vs);

    int qt = (int)gridDim.x - 1 - blockIdx.x;   // longest first
    int h = blockIdx.y, b = blockIdx.z;
    int tid = threadIdx.x, wid = tid >> 5, lane = tid & 31;
    int g = lane >> 2, tig = lane & 3;
    int wrow = wid * 16;
    long bh = (long)(b * Hc + h);
    const float* Qg = Q  + (bh * Tc + qt * 64) * HDc;
    const float* Kg = Kp + bh * Tc * HDc;
    const float* Vg = Vp + bh * Tc * HDc;

    // ldmatrix lane offsets (words)
    int aOffQ = (lane & 15) * QS_ + ((lane >> 4) << 2);
    int aOffP = (lane & 15) * KS_ + ((lane >> 4) << 2);     // P lives in K buf
    int bOffK = ((lane & 7) + ((lane >> 4) << 3)) * KS_ + (((lane >> 3) & 1) << 2);

    int sr = tid >> 4, sc4 = (tid & 15) << 2;   // staging row/col for this thread

    // prologue: stage Q and K(0) as ONE group
    {
        #pragma unroll
        for (int it = 0; it < 8; it++) {
            int row = sr + it * 8;
            cp_async16(Qsu  + (row * QS_ + sc4) * 4, Qg + row * 64 + sc4);
            cp_async16(Ks0u + (row * KS_ + sc4) * 4, Kg + row * 64 + sc4);
        }
        CP_COMMIT();
    }

    float m0 = -1e30f, m1 = -1e30f, l0 = 0.f, l1 = 0.f, ss0 = 0.f, ss1 = 0.f;
    float o_[8][4];
    #pragma unroll
    for (int i = 0; i < 8; i++)
        o_[i][0] = o_[i][1] = o_[i][2] = o_[i][3] = 0.f;

    int row_g0 = qt * 64 + wrow + g;
    int row_g1 = row_g0 + 8;

    for (int kt = 0; kt <= qt; kt++) {
        uint32_t Kbu = (kt & 1) ? Ks1u : Ks0u;      // K(kt) / P(kt)
        float*   Kb  = (kt & 1) ? Ks1  : Ks0;

        __syncthreads();          // prev PV readers done with Vs (and all smem)
        // issue V(kt)
        #pragma unroll
        for (int it = 0; it < 8; it++) {
            int row = sr + it * 8;
            cp_async16(Vsu + (row * VS_ + sc4) * 4,
                       Vg + (kt * 64 + row) * 64 + sc4);
        }
        CP_COMMIT();

        CP_WAIT1();               // K(kt) (and everything older) complete
        __syncthreads();          // K visible to all threads

        // ---- S = Q @ K^T (ldmatrix feeds) ----
        float s[8][4];
        #pragma unroll
        for (int nf = 0; nf < 8; nf++)
            s[nf][0] = s[nf][1] = s[nf][2] = s[nf][3] = 0.f;

        #pragma unroll
        for (int ks = 0; ks < 8; ks++) {
            int kk = ks * 8;
            unsigned a[4];
            ldsm_x4(a, Qsu + (wrow * QS_ + kk + aOffQ) * 4);
            unsigned bfr[4][4];
            #pragma unroll
            for (int np = 0; np < 4; np++)
                ldsm_x4(bfr[np], Kbu + ((np * 16) * KS_ + kk + bOffK) * 4);
            #pragma unroll
            for (int nf = 0; nf < 8; nf++)
                mma_tf32(s[nf], a, bfr[nf >> 1] + ((nf & 1) << 1));
        }

        __syncthreads();          // all warps done reading K(kt) -> P overlay OK;
                                  // other K buf free (K(kt-1)/P(kt-1) consumed)
        // issue K(kt+1) into the other buffer (empty commit keeps group count)
        if (kt < qt) {
            uint32_t Knu = (kt & 1) ? Ks0u : Ks1u;
            #pragma unroll
            for (int it = 0; it < 8; it++) {
                int row = sr + it * 8;
                cp_async16(Knu + (row * KS_ + sc4) * 4,
                           Kg + ((kt + 1) * 64 + row) * 64 + sc4);
            }
        }
        CP_COMMIT();

        // causal mask (diagonal tile only)
        if (kt == qt) {
            #pragma unroll
            for (int nf = 0; nf < 8; nf++) {
                int c = kt * 64 + nf * 8 + 2 * tig;
                if (c     > row_g0) s[nf][0] = -1e30f;
                if (c + 1 > row_g0) s[nf][1] = -1e30f;
                if (c     > row_g1) s[nf][2] = -1e30f;
                if (c + 1 > row_g1) s[nf][3] = -1e30f;
            }
        }

        float rm0 = -1e30f, rm1 = -1e30f;
        #pragma unroll
        for (int nf = 0; nf < 8; nf++) {
            rm0 = fmaxf(rm0, fmaxf(s[nf][0], s[nf][1]));
            rm1 = fmaxf(rm1, fmaxf(s[nf][2], s[nf][3]));
        }
        rm0 = fmaxf(rm0, __shfl_xor_sync(0xffffffffu, rm0, 1));
        rm0 = fmaxf(rm0, __shfl_xor_sync(0xffffffffu, rm0, 2));
        rm1 = fmaxf(rm1, __shfl_xor_sync(0xffffffffu, rm1, 1));
        rm1 = fmaxf(rm1, __shfl_xor_sync(0xffffffffu, rm1, 2));

        float mn0 = fmaxf(m0, rm0), mn1 = fmaxf(m1, rm1);
        float sc0 = fexp(m0 - mn0), sc1 = fexp(m1 - mn1);

        float rs0 = 0.f, rs1 = 0.f, rw0 = 0.f, rw1 = 0.f;
        float* prow0 = Kb + (wrow + g) * KS_ + 2 * tig;   // P overlays K(kt)
        float* prow1 = prow0 + 8 * KS_;
        #pragma unroll
        for (int nf = 0; nf < 8; nf++) {
            float p00 = fexp(s[nf][0] - mn0), p01 = fexp(s[nf][1] - mn0);
            float p10 = fexp(s[nf][2] - mn1), p11 = fexp(s[nf][3] - mn1);
            rs0 += p00 + p01; rw0 += p00 * s[nf][0] + p01 * s[nf][1];
            rs1 += p10 + p11; rw1 += p10 * s[nf][2] + p11 * s[nf][3];
            *(float2*)(prow0 + nf * 8) = make_float2(tf32f(p00), tf32f(p01));
            *(float2*)(prow1 + nf * 8) = make_float2(tf32f(p10), tf32f(p11));
        }
        #pragma unroll
        for (int o = 1; o <= 2; o <<= 1) {
            rs0 += __shfl_xor_sync(0xffffffffu, rs0, o);
            rw0 += __shfl_xor_sync(0xffffffffu, rw0, o);
            rs1 += __shfl_xor_sync(0xffffffffu, rs1, o);
            rw1 += __shfl_xor_sync(0xffffffffu, rw1, o);
        }
        l0 = l0 * sc0 + rs0;  ss0 = ss0 * sc0 + rw0;  m0 = mn0;
        l1 = l1 * sc1 + rs1;  ss1 = ss1 * sc1 + rw1;  m1 = mn1;

        #pragma unroll
        for (int nf = 0; nf < 8; nf++) {
            o_[nf][0] *= sc0; o_[nf][1] *= sc0;
            o_[nf][2] *= sc1; o_[nf][3] *= sc1;
        }

        CP_WAIT1();               // V(kt) complete (K(kt+1) may be in flight)
        __syncthreads();          // V visible to all; own-warp P writes done

        // ---- O += P @ V (P via ldmatrix from K-buf overlay, V scalar) ----
        #pragma unroll
        for (int ks = 0; ks < 8; ks++) {
            int kk = ks * 8;
            unsigned a[4];
            ldsm_x4(a, Kbu + (wrow * KS_ + kk + aOffP) * 4);
            const float* vbase = Vs + (kk + tig) * VS_ + g;
            #pragma unroll
            for (int nf = 0; nf < 8; nf++) {
                unsigned bb[2] = { __float_as_uint(vbase[nf * 8]),
                                   __float_as_uint(vbase[4 * VS_ + nf * 8]) };
                mma_tf32(o_[nf], a, bb);
            }
        }
    }

    float li0 = 1.f / l0, li1 = 1.f / l1;
    int t0 = qt * 64 + wrow + g;
    float* y0 = Y + ((long)(b * Tc + t0)) * Cc + h * 64 + 2 * tig;
    float* y1 = y0 + 8 * Cc;
    #pragma unroll
    for (int nf = 0; nf < 8; nf++) {
        *(float2*)(y0 + nf * 8) = make_float2(tf32f(o_[nf][0] * li0),
                                              tf32f(o_[nf][1] * li0));
        *(float2*)(y1 + nf * 8) = make_float2(tf32f(o_[nf][2] * li1),
                                              tf32f(o_[nf][3] * li1));
    }

    if (tig == 0) {
        Hs[wrow + g]     = m0 + logf(l0) - ss0 / l0;
        Hs[wrow + g + 8] = m1 + logf(l1) - ss1 / l1;
    }
    __syncthreads();
    if (tid == 0) {
        float sum = 0.f;
        #pragma unroll 8
        for (int i = 0; i < 64; i++) sum += Hs[i];
        atomicAdd(ent, sum * (1.0f / (float)(Bc * Hc * Tc)));
    }
}

// ---------------------------------------------------------------------------
extern "C" void kernel_launch(void* const* d_in, const int* in_sizes, int n_in,
                              void* d_out, int out_size)
{
    const float* x      = (const float*)d_in[0];
    const float* ln1w   = (const float*)d_in[1];
    const float* ln1b   = (const float*)d_in[2];
    const float* w_attn = (const float*)d_in[3];
    const float* b_attn = (const float*)d_in[4];
    const float* w_proj = (const float*)d_in[5];
    const float* b_proj = (const float*)d_in[6];
    const float* ln2w   = (const float*)d_in[7];
    const float* ln2b   = (const float*)d_in[8];
    const float* w_fc   = (const float*)d_in[9];
    const float* b_fc   = (const float*)d_in[10];
    const float* w_mlp  = (const float*)d_in[11];
    const float* b_mlp  = (const float*)d_in[12];

    float* out   = (float*)d_out;
    float* x1    = out;            // x output region
    float* ent   = out + XS;       // scalar entropy
    float* presK = out + XS + 1;   // present[0] (unaligned -- scalar only)
    float* presV = presK + PRES;   // present[1]

    float *ph, *pq, *pk, *pv, *pa, *pwa, *pwp, *pwf, *pwm;
    cudaGetSymbolAddress((void**)&ph,  g_h);
    cudaGetSymbolAddress((void**)&pq,  g_q);
    cudaGetSymbolAddress((void**)&pk,  g_k);
    cudaGetSymbolAddress((void**)&pv,  g_v);
    cudaGetSymbolAddress((void**)&pa,  g_a);
    cudaGetSymbolAddress((void**)&pwa, g_wa);
    cudaGetSymbolAddress((void**)&pwp, g_wp);
    cudaGetSymbolAddress((void**)&pwf, g_wf);
    cudaGetSymbolAddress((void**)&pwm, g_wm);

    cudaFuncSetAttribute(flash_mma_kernel,
                         cudaFuncAttributeMaxDynamicSharedMemorySize, FLASH_SMEM);
    cudaFuncSetAttribute(gemm_cp_kernel<0>,
                         cudaFuncAttributeMaxDynamicSharedMemorySize, GEMM_SMEM);
    cudaFuncSetAttribute(gemm_cp_kernel<1>,
                         cudaFuncAttributeMaxDynamicSharedMemorySize, GEMM_SMEM);
    cudaFuncSetAttribute(gemm_cp_kernel<2>,
                         cudaFuncAttributeMaxDynamicSharedMemorySize, GEMM_SMEM);

    // fused: zero entropy + tf32-round all weights (one launch)
    cvt_all_kernel<<<(N4_ALL + 255) / 256, 256>>>(
        (const float4*)w_attn, (const float4*)w_proj,
        (const float4*)w_fc,   (const float4*)w_mlp,
        (float4*)pwa, (float4*)pwp, (float4*)pwf, (float4*)pwm, ent);

    // h = LN1(x)  (tf32-rounded output)
    ln_kernel<<<Mrows, 256>>>(x, ln1w, ln1b, ph);

    // qkv = h @ w_attn^T + b_attn
    //   q (tf32, /8) -> g_q; k/v tf32 -> g_k/g_v; raw k/v -> present
    {
        dim3 g(3 * Cc / 128, Mrows / 128);
        gemm_cp_kernel<0><<<g, 256, GEMM_SMEM>>>(ph, pwa, b_attn, nullptr,
                                                 pq, pk, pv, presK, presV,
                                                 Cc, 3 * Cc);
    }

    // flash attention: y -> g_h (tf32-rounded), entropy -> ent
    {
        dim3 g(Tc / 64, Hc, Bc);
        flash_mma_kernel<<<g, 128, FLASH_SMEM>>>(pq, pk, pv, ph, ent);
    }

    // x1 = x + y @ w_proj^T + b_proj
    {
        dim3 g(Cc / 128, Mrows / 128);
        gemm_cp_kernel<1><<<g, 256, GEMM_SMEM>>>(ph, pwp, b_proj, x,
                                                 x1, nullptr, nullptr, nullptr, nullptr,
                                                 Cc, Cc);
    }

    // h2 = LN2(x1) -> g_h  (tf32-rounded)
    ln_kernel<<<Mrows, 256>>>(x1, ln2w, ln2b, ph);

    // a = gelu(h2 @ w_fc^T + b_fc) -> g_a  (tf32-rounded in epilogue)
    {
        dim3 g(4 * Cc / 128, Mrows / 128);
        gemm_cp_kernel<2><<<g, 256, GEMM_SMEM>>>(ph, pwf, b_fc, nullptr,
                                                 pa, nullptr, nullptr, nullptr, nullptr,
                                                 Cc, 4 * Cc);
    }

    // x_out = x1 + a @ w_mlp^T + b_mlp
    {
        dim3 g(Cc / 128, Mrows / 128);
        gemm_cp_kernel<1><<<g, 256, GEMM_SMEM>>>(pa, pwm, b_mlp, x1,
                                                 x1, nullptr, nullptr, nullptr, nullptr,
                                                 4 * Cc, Cc);
    }
}

// round 16
// speedup vs baseline: 1.4721x; 1.4721x over previous
#include <cuda_runtime.h>
#include <cuda_fp16.h>
#include <math.h>
#include <stdint.h>

// ---------------------------------------------------------------------------
// GPT transformer block. GEMMs on fp16 mma.sync m16n8k16 (fp32 accum),
// flash on tf32 mma.sync (tcgen05 unavailable: harness targets sm_103).
// GEMM: 128x128 CTA tile, 2 CTAs/SM, BK=64 halves, 3-stage cp.async,
// ldmatrix feeds. Flash: 64-row q-tile, double-buffered K (P overlays K),
// ldmatrix Q/K/P, longest-first order.
//   B=2, T=2048, C=1024, H=16, HD=64
// Output layout (float32): [ x (B*T*C) | att_entropy (1) | present (2*B*H*T*HD) ]
// present region starts at float offset XS+1 -> NOT 16B aligned (scalar only).
// ---------------------------------------------------------------------------

namespace {
constexpr int Bc = 2, Tc = 2048, Cc = 1024, Hc = 16, HDc = 64;
constexpr int Mrows = Bc * Tc;            // 4096
constexpr int XS    = Bc * Tc * Cc;       // 4194304
constexpr int PRES  = Bc * Hc * Tc * HDc; // 4194304

// flash smem strides (words) -- conflict-free fragment loads
constexpr int QS_ = 68, KS_ = 68, VS_ = 72;
constexpr int FLASH_SMEM = (64*QS_ + 2*64*KS_ + 64*VS_ + 64) * 4; // 70912 B

// fp16 GEMM: 128(M) x 128(N) CTA tile, BK=64 halves, 3 stages, 2 CTAs/SM
constexpr int TS16  = 72;                  // row stride halves (144B)
constexpr int STG   = 3;
constexpr int ATILE16 = 128 * TS16;        // halves per operand per stage
constexpr int GEMM_SMEM = STG * 2 * ATILE16 * 2; // 110592 B

// fused weight-cvt sizes (float4 units)
constexpr int N4_A = 3 * Cc * Cc / 4;
constexpr int N4_P = Cc * Cc / 4;
constexpr int N4_F = Cc * Cc;
constexpr int N4_M = Cc * Cc;
constexpr int N4_ALL = N4_A + N4_P + N4_F + N4_M; // 3145728
}

// scratch (device globals -- no allocations allowed)
__device__ __half g_h[Mrows * Cc];        // LN outputs / flash y (fp16)
__device__ float  g_q[PRES];              // Q tf32, pre-scaled 1/8 (B,H,T,HD)
__device__ float  g_k[PRES];              // K tf32 (B,H,T,HD)
__device__ float  g_v[PRES];              // V tf32 (B,H,T,HD)
__device__ __half g_a[Mrows * 4 * Cc];    // FC activation (fp16)
__device__ __half g_wa[3 * Cc * Cc];      // fp16 w_attn
__device__ __half g_wp[Cc * Cc];          // fp16 w_proj
__device__ __half g_wf[4 * Cc * Cc];      // fp16 w_fc
__device__ __half g_wm[4 * Cc * Cc];      // fp16 w_mlp

// ---------------------------------------------------------------------------
__device__ __forceinline__ uint32_t smem_u32(const void* p) {
    uint32_t a;
    asm("{ .reg .u64 t; cvta.to.shared.u64 t, %1; cvt.u32.u64 %0, t; }"
        : "=r"(a) : "l"(p));
    return a;
}
__device__ __forceinline__ void cp_async16(uint32_t dst, const void* src) {
    asm volatile("cp.async.cg.shared.global [%0], [%1], 16;"
                 :: "r"(dst), "l"(src));
}
#define CP_COMMIT() asm volatile("cp.async.commit_group;" ::: "memory")
#define CP_WAIT1()  asm volatile("cp.async.wait_group 1;"  ::: "memory")

__device__ __forceinline__ void ldsm_x4(unsigned* r, uint32_t addr) {
    asm volatile("ldmatrix.sync.aligned.m8n8.x4.shared.b16 {%0,%1,%2,%3}, [%4];"
                 : "=r"(r[0]), "=r"(r[1]), "=r"(r[2]), "=r"(r[3]) : "r"(addr));
}
__device__ __forceinline__ unsigned f2tf32(float f) {
    unsigned u;
    asm("cvt.rna.tf32.f32 %0, %1;" : "=r"(u) : "f"(f));
    return u;
}
__device__ __forceinline__ float tf32f(float f) {
    return __uint_as_float(f2tf32(f));
}
__device__ __forceinline__ void mma_tf32(float* c, const unsigned* a, const unsigned* b) {
    asm volatile(
        "mma.sync.aligned.m16n8k8.row.col.f32.tf32.tf32.f32 "
        "{%0,%1,%2,%3},{%4,%5,%6,%7},{%8,%9},{%0,%1,%2,%3};"
        : "+f"(c[0]), "+f"(c[1]), "+f"(c[2]), "+f"(c[3])
        : "r"(a[0]), "r"(a[1]), "r"(a[2]), "r"(a[3]), "r"(b[0]), "r"(b[1]));
}
__device__ __forceinline__ void mma_f16(float* c, const unsigned* a, const unsigned* b) {
    asm volatile(
        "mma.sync.aligned.m16n8k16.row.col.f32.f16.f16.f32 "
        "{%0,%1,%2,%3},{%4,%5,%6,%7},{%8,%9},{%0,%1,%2,%3};"
        : "+f"(c[0]), "+f"(c[1]), "+f"(c[2]), "+f"(c[3])
        : "r"(a[0]), "r"(a[1]), "r"(a[2]), "r"(a[3]), "r"(b[0]), "r"(b[1]));
}
__device__ __forceinline__ float gelu_f(float v) {
    const float c = 0.7978845608028654f;
    float u = c * (v + 0.044715f * v * v * v);
    return 0.5f * v * (1.0f + tanhf(u));
}
// fast exp on the FMA pipe (no MUFU). rel err ~4e-5.
__device__ __forceinline__ float fexp(float x) {
    x = fmaxf(x, -87.0f);
    float z = x * 1.442695041f;
    float t = z + 12582912.0f;
    float n = t - 12582912.0f;
    float r = z - n;
    float p = 9.61812910e-3f;
    p = fmaf(p, r, 5.55041087e-2f);
    p = fmaf(p, r, 2.40226507e-1f);
    p = fmaf(p, r, 6.93147182e-1f);
    p = fmaf(p, r, 1.0f);
    return __int_as_float(__float_as_int(p) + (__float_as_int(t) << 23));
}

// ---------------------------------------------------------------------------
// fused: zero entropy + fp16-convert all four weight matrices
__global__ void cvt_all_kernel(const float4* __restrict__ wa,
                               const float4* __restrict__ wp,
                               const float4* __restrict__ wf,
                               const float4* __restrict__ wm,
                               __half* __restrict__ oa,
                               __half* __restrict__ op,
                               __half* __restrict__ of,
                               __half* __restrict__ om,
                               float* __restrict__ ent)
{
    long i = (long)blockIdx.x * 256 + threadIdx.x;
    if (i == 0) *ent = 0.0f;
    if (i >= N4_ALL) return;
    const float4* src; __half* dst; long j = i;
    if (j < N4_A)            { src = wa; dst = oa; }
    else if ((j -= N4_A) < N4_P) { src = wp; dst = op; }
    else if ((j -= N4_P) < N4_F) { src = wf; dst = of; }
    else { j -= N4_F;          src = wm; dst = om; }
    float4 v = src[j];
    __half2* d2 = (__half2*)(dst + j * 4);
    d2[0] = __floats2half2_rn(v.x, v.y);
    d2[1] = __floats2half2_rn(v.z, v.w);
}

// ---------------------------------------------------------------------------
// LayerNorm: one block per row, 256 threads, 1 float4/thread; fp16 output.
__global__ void ln_kernel(const float* __restrict__ x,
                          const float* __restrict__ w,
                          const float* __restrict__ b,
                          __half* __restrict__ out)
{
    int row = blockIdx.x, tid = threadIdx.x;
    float4 v = ((const float4*)(x + (long)row * Cc))[tid];
    float s  = v.x + v.y + v.z + v.w;
    float s2 = v.x*v.x + v.y*v.y + v.z*v.z + v.w*v.w;
    __shared__ float rs[8], rs2[8];
    #pragma unroll
    for (int o = 16; o; o >>= 1) {
        s  += __shfl_xor_sync(0xffffffffu, s,  o);
        s2 += __shfl_xor_sync(0xffffffffu, s2, o);
    }
    int lane = tid & 31, wid = tid >> 5;
    if (lane == 0) { rs[wid] = s; rs2[wid] = s2; }
    __syncthreads();
    if (wid == 0) {
        s  = (lane < 8) ? rs[lane]  : 0.f;
        s2 = (lane < 8) ? rs2[lane] : 0.f;
        #pragma unroll
        for (int o = 4; o; o >>= 1) {
            s  += __shfl_xor_sync(0xffffffffu, s,  o);
            s2 += __shfl_xor_sync(0xffffffffu, s2, o);
        }
        if (lane == 0) { rs[0] = s; rs2[0] = s2; }
    }
    __syncthreads();
    float mean = rs[0] * (1.0f / Cc);
    float var  = rs2[0] * (1.0f / Cc) - mean * mean;
    float inv  = rsqrtf(var + 1e-5f);
    float4 w4 = ((const float4*)w)[tid];
    float4 b4 = ((const float4*)b)[tid];
    __half2* o2 = (__half2*)(out + (long)row * Cc + tid * 4);
    o2[0] = __floats2half2_rn((v.x - mean) * inv * w4.x + b4.x,
                              (v.y - mean) * inv * w4.y + b4.y);
    o2[1] = __floats2half2_rn((v.z - mean) * inv * w4.z + b4.z,
                              (v.w - mean) * inv * w4.w + b4.w);
}

// ---------------------------------------------------------------------------
// fp16 mma.sync GEMM: C[M,N] = A[M,K] @ W[N,K]^T (+bias, +epilogue).
// A, W fp16; fp32 accumulate. CTA tile 128x128, BK=64 halves, 3 stages,
// 8 warps (2m x 4n), 64x32 warp tile, m16n8k16, ldmatrix feeds, 2 CTAs/SM.
// EPI: 0 = QKV scatter (q tf32/8 + k/v tf32 -> scratch, raw -> present)
//      1 = fp32 out = acc + bias + res
//      2 = fp16 out = gelu(acc + bias)
template <int EPI>
__global__ __launch_bounds__(256, 2)
void gemm_f16_kernel(const __half* __restrict__ A,
                     const __half* __restrict__ W,
                     const float* __restrict__ bias,
                     const float* __restrict__ res,
                     float* __restrict__ outp,
                     float* __restrict__ out_k,
                     float* __restrict__ out_v,
                     float* __restrict__ pres_k,
                     float* __restrict__ pres_v,
                     int K, int N)
{
    extern __shared__ __half sh16[];
    __half* sA = sh16;                      // [STG][128][TS16]
    __half* sB = sh16 + STG * ATILE16;      // [STG][128][TS16]
    uint32_t sAu = smem_u32(sA), sBu = smem_u32(sB);

    int tid = threadIdx.x;
    int mbase = blockIdx.y * 128, nbase = blockIdx.x * 128;
    int wid = tid >> 5, lane = tid & 31;
    int g = lane >> 2, tig = lane & 3;
    int wm = wid >> 2, wn = wid & 3;     // 2 x 4 warp grid
    int moff = wm * 64, noff = wn * 32;
    int nst = K >> 6;                    // BK = 64 halves

    float acc[4][4][4] = {};             // 64x32 per warp

    // ldmatrix lane offsets (halves):
    //  A x4 (m16k16): lanes 0-15 rows 0-15 @k-lo8; 16-31 rows 0-15 @k-hi8
    //  B x4 (2 x n8k16): lanes 0-7 n0-7@k-lo, 8-15 n0-7@k-hi,
    //                    16-23 n8-15@k-lo, 24-31 n8-15@k-hi
    int aOff = (lane & 15) * TS16 + ((lane >> 4) << 3);
    int bOff = ((lane & 7) + ((lane >> 4) << 3)) * TS16 + (((lane >> 3) & 1) << 3);

    // one 16B slot of chunk st (4 slots per op per thread per chunk)
    auto issueQ = [&](int st, int q) {
        if (st < nst) {
            int k0 = st << 6, buf = st % STG;
            int id = tid + (q << 8);
            int row = id >> 3, c8 = (id & 7) << 3;    // 8 halves = 16B
            uint32_t off = ((buf * 128 + row) * TS16 + c8) * 2;
            cp_async16(sAu + off, A + (long)(mbase + row) * K + k0 + c8);
            cp_async16(sBu + off, W + (long)(nbase + row) * K + k0 + c8);
        }
    };
    auto issueAll = [&](int st) {
        #pragma unroll
        for (int q = 0; q < 4; q++) issueQ(st, q);
        CP_COMMIT();
    };

    issueAll(0);
    issueAll(1);

    for (int it = 0; it < nst; it++) {
        CP_WAIT1();
        __syncthreads();

        uint32_t cAu = sAu + ((it % STG) * ATILE16) * 2;
        uint32_t cBu = sBu + ((it % STG) * ATILE16) * 2;
        #pragma unroll
        for (int x = 0; x < 4; x++) {
            issueQ(it + 2, x);
            int kk = x * 16;                          // k16 per step
            unsigned afr[4][4], bfr[2][4];
            #pragma unroll
            for (int mf = 0; mf < 4; mf++)
                ldsm_x4(afr[mf],
                        cAu + (((moff + mf * 16) * TS16) + kk + aOff) * 2);
            #pragma unroll
            for (int np = 0; np < 2; np++)
                ldsm_x4(bfr[np],
                        cBu + (((noff + np * 16) * TS16) + kk + bOff) * 2);
            #pragma unroll
            for (int mf = 0; mf < 4; mf++) {
                #pragma unroll
                for (int nf = 0; nf < 4; nf++)
                    mma_f16(acc[mf][nf], afr[mf], bfr[nf >> 1] + ((nf & 1) << 1));
            }
        }
        CP_COMMIT();
    }

    if (EPI == 0) {
        int region = nbase >> 10;
        float* dst  = (region == 0) ? outp : (region == 1) ? out_k  : out_v;
        float* dst2 = (region == 0) ? (float*)0
                    : (region == 1) ? pres_k : pres_v;
        #pragma unroll
        for (int mf = 0; mf < 4; mf++) {
            #pragma unroll
            for (int i = 0; i < 2; i++) {
                int row = mbase + moff + mf * 16 + g + i * 8;
                int bidx = row >> 11;
                int t    = row & (Tc - 1);
                #pragma unroll
                for (int nf = 0; nf < 4; nf++) {
                    int n = nbase + noff + nf * 8 + tig * 2;
                    float2 v;
                    v.x = acc[mf][nf][i * 2 + 0] + bias[n];
                    v.y = acc[mf][nf][i * 2 + 1] + bias[n + 1];
                    int nl = n & (Cc - 1);
                    int head = nl >> 6, d = nl & 63;
                    long idx = (((long)(bidx * Hc + head) * Tc) + t) * HDc + d;
                    if (region == 0) {
                        *(float2*)(dst + idx) =
                            make_float2(tf32f(v.x * 0.125f), tf32f(v.y * 0.125f));
                    } else {
                        *(float2*)(dst + idx) =
                            make_float2(tf32f(v.x), tf32f(v.y));
                        dst2[idx] = v.x; dst2[idx + 1] = v.y;
                    }
                }
            }
        }
    } else {
        #pragma unroll
        for (int mf = 0; mf < 4; mf++) {
            #pragma unroll
            for (int i = 0; i < 2; i++) {
                int row = mbase + moff + mf * 16 + g + i * 8;
                #pragma unroll
                for (int nf = 0; nf < 4; nf++) {
                    int n = nbase + noff + nf * 8 + tig * 2;
                    long idx = (long)row * N + n;
                    float2 v;
                    v.x = acc[mf][nf][i * 2 + 0] + bias[n];
                    v.y = acc[mf][nf][i * 2 + 1] + bias[n + 1];
                    if (EPI == 1) {
                        float2 r2 = *(const float2*)(res + idx);
                        v.x += r2.x; v.y += r2.y;
                        *(float2*)(outp + idx) = v;
                    } else {
                        __half* o16 = reinterpret_cast<__half*>(outp);
                        *(__half2*)(o16 + idx) =
                            __floats2half2_rn(gelu_f(v.x), gelu_f(v.y));
                    }
                }
            }
        }
    }
}

// ---------------------------------------------------------------------------
// Flash attention: 64-row q-tile, 4 warps x 16 rows, tf32 mma.sync.
// K double-buffered (P overlays current K), V hidden behind S+softmax,
// ldmatrix Q/K/P, longest-first order. Y written as fp16 (proj GEMM input).
__global__ __launch_bounds__(128, 3)
void flash_mma_kernel(const float* __restrict__ Q,
                      const float* __restrict__ Kp,
                      const float* __restrict__ Vp,
                      __half* __restrict__ Y,
                      float* __restrict__ ent)
{
    extern __shared__ float sm[];
    float* Qs  = sm;
    float* Ks0 = Qs  + 64 * QS_;
    float* Ks1 = Ks0 + 64 * KS_;
    float* Vs  = Ks1 + 64 * KS_;
    float* Hs  = Vs  + 64 * VS_;
    uint32_t Qsu  = smem_u32(Qs);
    uint32_t Ks0u = smem_u32(Ks0), Ks1u = smem_u32(Ks1);
    uint32_t Vsu  = smem_u32(Vs);

    int qt = (int)gridDim.x - 1 - blockIdx.x;   // longest first
    int h = blockIdx.y, b = blockIdx.z;
    int tid = threadIdx.x, wid = tid >> 5, lane = tid & 31;
    int g = lane >> 2, tig = lane & 3;
    int wrow = wid * 16;
    long bh = (long)(b * Hc + h);
    const float* Qg = Q  + (bh * Tc + qt * 64) * HDc;
    const float* Kg = Kp + bh * Tc * HDc;
    const float* Vg = Vp + bh * Tc * HDc;

    int aOffQ = (lane & 15) * QS_ + ((lane >> 4) << 2);
    int aOffP = (lane & 15) * KS_ + ((lane >> 4) << 2);
    int bOffK = ((lane & 7) + ((lane >> 4) << 3)) * KS_ + (((lane >> 3) & 1) << 2);

    int sr = tid >> 4, sc4 = (tid & 15) << 2;

    {
        #pragma unroll
        for (int it = 0; it < 8; it++) {
            int row = sr + it * 8;
            cp_async16(Qsu  + (row * QS_ + sc4) * 4, Qg + row * 64 + sc4);
            cp_async16(Ks0u + (row * KS_ + sc4) * 4, Kg + row * 64 + sc4);
        }
        CP_COMMIT();
    }

    float m0 = -1e30f, m1 = -1e30f, l0 = 0.f, l1 = 0.f, ss0 = 0.f, ss1 = 0.f;
    float o_[8][4];
    #pragma unroll
    for (int i = 0; i < 8; i++)
        o_[i][0] = o_[i][1] = o_[i][2] = o_[i][3] = 0.f;

    int row_g0 = qt * 64 + wrow + g;
    int row_g1 = row_g0 + 8;

    for (int kt = 0; kt <= qt; kt++) {
        uint32_t Kbu = (kt & 1) ? Ks1u : Ks0u;
        float*   Kb  = (kt & 1) ? Ks1  : Ks0;

        __syncthreads();
        #pragma unroll
        for (int it = 0; it < 8; it++) {
            int row = sr + it * 8;
            cp_async16(Vsu + (row * VS_ + sc4) * 4,
                       Vg + (kt * 64 + row) * 64 + sc4);
        }
        CP_COMMIT();

        CP_WAIT1();
        __syncthreads();

        float s[8][4];
        #pragma unroll
        for (int nf = 0; nf < 8; nf++)
            s[nf][0] = s[nf][1] = s[nf][2] = s[nf][3] = 0.f;

        #pragma unroll
        for (int ks = 0; ks < 8; ks++) {
            int kk = ks * 8;
            unsigned a[4];
            ldsm_x4(a, Qsu + (wrow * QS_ + kk + aOffQ) * 4);
            unsigned bfr[4][4];
            #pragma unroll
            for (int np = 0; np < 4; np++)
                ldsm_x4(bfr[np], Kbu + ((np * 16) * KS_ + kk + bOffK) * 4);
            #pragma unroll
            for (int nf = 0; nf < 8; nf++)
                mma_tf32(s[nf], a, bfr[nf >> 1] + ((nf & 1) << 1));
        }

        __syncthreads();
        if (kt < qt) {
            uint32_t Knu = (kt & 1) ? Ks0u : Ks1u;
            #pragma unroll
            for (int it = 0; it < 8; it++) {
                int row = sr + it * 8;
                cp_async16(Knu + (row * KS_ + sc4) * 4,
                           Kg + ((kt + 1) * 64 + row) * 64 + sc4);
            }
        }
        CP_COMMIT();

        if (kt == qt) {
            #pragma unroll
            for (int nf = 0; nf < 8; nf++) {
                int c = kt * 64 + nf * 8 + 2 * tig;
                if (c     > row_g0) s[nf][0] = -1e30f;
                if (c + 1 > row_g0) s[nf][1] = -1e30f;
                if (c     > row_g1) s[nf][2] = -1e30f;
                if (c + 1 > row_g1) s[nf][3] = -1e30f;
            }
        }

        float rm0 = -1e30f, rm1 = -1e30f;
        #pragma unroll
        for (int nf = 0; nf < 8; nf++) {
            rm0 = fmaxf(rm0, fmaxf(s[nf][0], s[nf][1]));
            rm1 = fmaxf(rm1, fmaxf(s[nf][2], s[nf][3]));
        }
        rm0 = fmaxf(rm0, __shfl_xor_sync(0xffffffffu, rm0, 1));
        rm0 = fmaxf(rm0, __shfl_xor_sync(0xffffffffu, rm0, 2));
        rm1 = fmaxf(rm1, __shfl_xor_sync(0xffffffffu, rm1, 1));
        rm1 = fmaxf(rm1, __shfl_xor_sync(0xffffffffu, rm1, 2));

        float mn0 = fmaxf(m0, rm0), mn1 = fmaxf(m1, rm1);
        float sc0 = fexp(m0 - mn0), sc1 = fexp(m1 - mn1);

        float rs0 = 0.f, rs1 = 0.f, rw0 = 0.f, rw1 = 0.f;
        float* prow0 = Kb + (wrow + g) * KS_ + 2 * tig;
        float* prow1 = prow0 + 8 * KS_;
        #pragma unroll
        for (int nf = 0; nf < 8; nf++) {
            float p00 = fexp(s[nf][0] - mn0), p01 = fexp(s[nf][1] - mn0);
            float p10 = fexp(s[nf][2] - mn1), p11 = fexp(s[nf][3] - mn1);
            rs0 += p00 + p01; rw0 += p00 * s[nf][0] + p01 * s[nf][1];
            rs1 += p10 + p11; rw1 += p10 * s[nf][2] + p11 * s[nf][3];
            *(float2*)(prow0 + nf * 8) = make_float2(tf32f(p00), tf32f(p01));
            *(float2*)(prow1 + nf * 8) = make_float2(tf32f(p10), tf32f(p11));
        }
        #pragma unroll
        for (int o = 1; o <= 2; o <<= 1) {
            rs0 += __shfl_xor_sync(0xffffffffu, rs0, o);
            rw0 += __shfl_xor_sync(0xffffffffu, rw0, o);
            rs1 += __shfl_xor_sync(0xffffffffu, rs1, o);
            rw1 += __shfl_xor_sync(0xffffffffu, rw1, o);
        }
        l0 = l0 * sc0 + rs0;  ss0 = ss0 * sc0 + rw0;  m0 = mn0;
        l1 = l1 * sc1 + rs1;  ss1 = ss1 * sc1 + rw1;  m1 = mn1;

        #pragma unroll
        for (int nf = 0; nf < 8; nf++) {
            o_[nf][0] *= sc0; o_[nf][1] *= sc0;
            o_[nf][2] *= sc1; o_[nf][3] *= sc1;
        }

        CP_WAIT1();
        __syncthreads();

        #pragma unroll
        for (int ks = 0; ks < 8; ks++) {
            int kk = ks * 8;
            unsigned a[4];
            ldsm_x4(a, Kbu + (wrow * KS_ + kk + aOffP) * 4);
            const float* vbase = Vs + (kk + tig) * VS_ + g;
            #pragma unroll
            for (int nf = 0; nf < 8; nf++) {
                unsigned bb[2] = { __float_as_uint(vbase[nf * 8]),
                                   __float_as_uint(vbase[4 * VS_ + nf * 8]) };
                mma_tf32(o_[nf], a, bb);
            }
        }
    }

    float li0 = 1.f / l0, li1 = 1.f / l1;
    int t0 = qt * 64 + wrow + g;
    __half* y0 = Y + ((long)(b * Tc + t0)) * Cc + h * 64 + 2 * tig;
    __half* y1 = y0 + 8 * Cc;
    #pragma unroll
    for (int nf = 0; nf < 8; nf++) {
        *(__half2*)(y0 + nf * 8) = __floats2half2_rn(o_[nf][0] * li0,
                                                     o_[nf][1] * li0);
        *(__half2*)(y1 + nf * 8) = __floats2half2_rn(o_[nf][2] * li1,
                                                     o_[nf][3] * li1);
    }

    if (tig == 0) {
        Hs[wrow + g]     = m0 + logf(l0) - ss0 / l0;
        Hs[wrow + g + 8] = m1 + logf(l1) - ss1 / l1;
    }
    __syncthreads();
    if (tid == 0) {
        float sum = 0.f;
        #pragma unroll 8
        for (int i = 0; i < 64; i++) sum += Hs[i];
        atomicAdd(ent, sum * (1.0f / (float)(Bc * Hc * Tc)));
    }
}

// ---------------------------------------------------------------------------
extern "C" void kernel_launch(void* const* d_in, const int* in_sizes, int n_in,
                              void* d_out, int out_size)
{
    const float* x      = (const float*)d_in[0];
    const float* ln1w   = (const float*)d_in[1];
    const float* ln1b   = (const float*)d_in[2];
    const float* w_attn = (const float*)d_in[3];
    const float* b_attn = (const float*)d_in[4];
    const float* w_proj = (const float*)d_in[5];
    const float* b_proj = (const float*)d_in[6];
    const float* ln2w   = (const float*)d_in[7];
    const float* ln2b   = (const float*)d_in[8];
    const float* w_fc   = (const float*)d_in[9];
    const float* b_fc   = (const float*)d_in[10];
    const float* w_mlp  = (const float*)d_in[11];
    const float* b_mlp  = (const float*)d_in[12];

    float* out   = (float*)d_out;
    float* x1    = out;            // x output region
    float* ent   = out + XS;       // scalar entropy
    float* presK = out + XS + 1;   // present[0] (unaligned -- scalar only)
    float* presV = presK + PRES;   // present[1]

    __half *ph, *pa, *pwa, *pwp, *pwf, *pwm;
    float *pq, *pk, *pv;
    cudaGetSymbolAddress((void**)&ph,  g_h);
    cudaGetSymbolAddress((void**)&pq,  g_q);
    cudaGetSymbolAddress((void**)&pk,  g_k);
    cudaGetSymbolAddress((void**)&pv,  g_v);
    cudaGetSymbolAddress((void**)&pa,  g_a);
    cudaGetSymbolAddress((void**)&pwa, g_wa);
    cudaGetSymbolAddress((void**)&pwp, g_wp);
    cudaGetSymbolAddress((void**)&pwf, g_wf);
    cudaGetSymbolAddress((void**)&pwm, g_wm);

    cudaFuncSetAttribute(flash_mma_kernel,
                         cudaFuncAttributeMaxDynamicSharedMemorySize, FLASH_SMEM);
    cudaFuncSetAttribute(gemm_f16_kernel<0>,
                         cudaFuncAttributeMaxDynamicSharedMemorySize, GEMM_SMEM);
    cudaFuncSetAttribute(gemm_f16_kernel<1>,
                         cudaFuncAttributeMaxDynamicSharedMemorySize, GEMM_SMEM);
    cudaFuncSetAttribute(gemm_f16_kernel<2>,
                         cudaFuncAttributeMaxDynamicSharedMemorySize, GEMM_SMEM);

    // fused: zero entropy + fp16-convert all weights (one launch)
    cvt_all_kernel<<<(N4_ALL + 255) / 256, 256>>>(
        (const float4*)w_attn, (const float4*)w_proj,
        (const float4*)w_fc,   (const float4*)w_mlp,
        pwa, pwp, pwf, pwm, ent);

    // h = LN1(x)  (fp16 output)
    ln_kernel<<<Mrows, 256>>>(x, ln1w, ln1b, ph);

    // qkv = h @ w_attn^T + b_attn
    //   q (tf32,/8) -> g_q; k/v tf32 -> g_k/g_v; raw k/v -> present
    {
        dim3 g(3 * Cc / 128, Mrows / 128);
        gemm_f16_kernel<0><<<g, 256, GEMM_SMEM>>>(ph, pwa, b_attn, nullptr,
                                                  pq, pk, pv, presK, presV,
                                                  Cc, 3 * Cc);
    }

    // flash attention: y -> g_h (fp16), entropy -> ent
    {
        dim3 g(Tc / 64, Hc, Bc);
        flash_mma_kernel<<<g, 128, FLASH_SMEM>>>(pq, pk, pv, ph, ent);
    }

    // x1 = x + y @ w_proj^T + b_proj
    {
        dim3 g(Cc / 128, Mrows / 128);
        gemm_f16_kernel<1><<<g, 256, GEMM_SMEM>>>(ph, pwp, b_proj, x,
                                                  x1, nullptr, nullptr, nullptr, nullptr,
                                                  Cc, Cc);
    }

    // h2 = LN2(x1) -> g_h  (fp16)
    ln_kernel<<<Mrows, 256>>>(x1, ln2w, ln2b, ph);

    // a = gelu(h2 @ w_fc^T + b_fc) -> g_a  (fp16 in epilogue)
    {
        dim3 g(4 * Cc / 128, Mrows / 128);
        gemm_f16_kernel<2><<<g, 256, GEMM_SMEM>>>(ph, pwf, b_fc, nullptr,
                                                  (float*)pa, nullptr, nullptr, nullptr, nullptr,
                                                  Cc, 4 * Cc);
    }

    // x_out = x1 + a @ w_mlp^T + b_mlp
    {
        dim3 g(Cc / 128, Mrows / 128);
        gemm_f16_kernel<1><<<g, 256, GEMM_SMEM>>>(pa, pwm, b_mlp, x1,
                                                  x1, nullptr, nullptr, nullptr, nullptr,
                                                  4 * Cc, Cc);
    }
}

// round 17
// speedup vs baseline: 1.7317x; 1.1764x over previous
#include <cuda_runtime.h>
#include <cuda_fp16.h>
#include <math.h>
#include <stdint.h>

// ---------------------------------------------------------------------------
// GPT transformer block. GEMMs AND flash on fp16 mma.sync m16n8k16 (fp32
// accum). tcgen05 unavailable (harness targets sm_103 w/o 'a' features).
// GEMM: 128x128 CTA tile, 2 CTAs/SM, BK=64 halves, 3-stage cp.async, ldsm.
// Flash: 64-row q-tile, fp16 Q/K/V, double-buffered K (P overlays K),
// V via ldmatrix.trans, longest-first order.
//   B=2, T=2048, C=1024, H=16, HD=64
// Output layout (float32): [ x (B*T*C) | att_entropy (1) | present (2*B*H*T*HD) ]
// present region starts at float offset XS+1 -> NOT 16B aligned (scalar only).
// ---------------------------------------------------------------------------

namespace {
constexpr int Bc = 2, Tc = 2048, Cc = 1024, Hc = 16, HDc = 64;
constexpr int Mrows = Bc * Tc;            // 4096
constexpr int XS    = Bc * Tc * Cc;       // 4194304
constexpr int PRES  = Bc * Hc * Tc * HDc; // 4194304

// flash smem strides in HALVES (stride 72 = 36 words = 4 mod 32: conflict-free)
constexpr int QSh = 72, KSh = 72, VSh = 72;
constexpr int FLASH_SMEM = (64*QSh + 2*64*KSh + 64*VSh) * 2 + 64 * 4; // 37120 B

// fp16 GEMM: 128(M) x 128(N) CTA tile, BK=64 halves, 3 stages, 2 CTAs/SM
constexpr int TS16  = 72;                  // row stride halves (144B)
constexpr int STG   = 3;
constexpr int ATILE16 = 128 * TS16;        // halves per operand per stage
constexpr int GEMM_SMEM = STG * 2 * ATILE16 * 2; // 110592 B

// fused weight-cvt sizes (float4 units)
constexpr int N4_A = 3 * Cc * Cc / 4;
constexpr int N4_P = Cc * Cc / 4;
constexpr int N4_F = Cc * Cc;
constexpr int N4_M = Cc * Cc;
constexpr int N4_ALL = N4_A + N4_P + N4_F + N4_M; // 3145728
}

// scratch (device globals -- no allocations allowed)
__device__ __half g_h[Mrows * Cc];        // LN outputs / flash y (fp16)
__device__ __half g_q[PRES];              // Q fp16, pre-scaled 1/8 (B,H,T,HD)
__device__ __half g_k[PRES];              // K fp16 (B,H,T,HD)
__device__ __half g_v[PRES];              // V fp16 (B,H,T,HD)
__device__ __half g_a[Mrows * 4 * Cc];    // FC activation (fp16)
__device__ __half g_wa[3 * Cc * Cc];      // fp16 w_attn
__device__ __half g_wp[Cc * Cc];          // fp16 w_proj
__device__ __half g_wf[4 * Cc * Cc];      // fp16 w_fc
__device__ __half g_wm[4 * Cc * Cc];      // fp16 w_mlp

// ---------------------------------------------------------------------------
__device__ __forceinline__ uint32_t smem_u32(const void* p) {
    uint32_t a;
    asm("{ .reg .u64 t; cvta.to.shared.u64 t, %1; cvt.u32.u64 %0, t; }"
        : "=r"(a) : "l"(p));
    return a;
}
__device__ __forceinline__ void cp_async16(uint32_t dst, const void* src) {
    asm volatile("cp.async.cg.shared.global [%0], [%1], 16;"
                 :: "r"(dst), "l"(src));
}
#define CP_COMMIT() asm volatile("cp.async.commit_group;" ::: "memory")
#define CP_WAIT1()  asm volatile("cp.async.wait_group 1;"  ::: "memory")

__device__ __forceinline__ void ldsm_x4(unsigned* r, uint32_t addr) {
    asm volatile("ldmatrix.sync.aligned.m8n8.x4.shared.b16 {%0,%1,%2,%3}, [%4];"
                 : "=r"(r[0]), "=r"(r[1]), "=r"(r[2]), "=r"(r[3]) : "r"(addr));
}
__device__ __forceinline__ void ldsm_x4_t(unsigned* r, uint32_t addr) {
    asm volatile("ldmatrix.sync.aligned.m8n8.x4.trans.shared.b16 {%0,%1,%2,%3}, [%4];"
                 : "=r"(r[0]), "=r"(r[1]), "=r"(r[2]), "=r"(r[3]) : "r"(addr));
}
__device__ __forceinline__ void mma_f16(float* c, const unsigned* a, const unsigned* b) {
    asm volatile(
        "mma.sync.aligned.m16n8k16.row.col.f32.f16.f16.f32 "
        "{%0,%1,%2,%3},{%4,%5,%6,%7},{%8,%9},{%0,%1,%2,%3};"
        : "+f"(c[0]), "+f"(c[1]), "+f"(c[2]), "+f"(c[3])
        : "r"(a[0]), "r"(a[1]), "r"(a[2]), "r"(a[3]), "r"(b[0]), "r"(b[1]));
}
__device__ __forceinline__ float gelu_f(float v) {
    const float c = 0.7978845608028654f;
    float u = c * (v + 0.044715f * v * v * v);
    return 0.5f * v * (1.0f + tanhf(u));
}
// fast exp on the FMA pipe (no MUFU). rel err ~4e-5.
__device__ __forceinline__ float fexp(float x) {
    x = fmaxf(x, -87.0f);
    float z = x * 1.442695041f;
    float t = z + 12582912.0f;
    float n = t - 12582912.0f;
    float r = z - n;
    float p = 9.61812910e-3f;
    p = fmaf(p, r, 5.55041087e-2f);
    p = fmaf(p, r, 2.40226507e-1f);
    p = fmaf(p, r, 6.93147182e-1f);
    p = fmaf(p, r, 1.0f);
    return __int_as_float(__float_as_int(p) + (__float_as_int(t) << 23));
}

// ---------------------------------------------------------------------------
// fused: zero entropy + fp16-convert all four weight matrices
__global__ void cvt_all_kernel(const float4* __restrict__ wa,
                               const float4* __restrict__ wp,
                               const float4* __restrict__ wf,
                               const float4* __restrict__ wm,
                               __half* __restrict__ oa,
                               __half* __restrict__ op,
                               __half* __restrict__ of,
                               __half* __restrict__ om,
                               float* __restrict__ ent)
{
    long i = (long)blockIdx.x * 256 + threadIdx.x;
    if (i == 0) *ent = 0.0f;
    if (i >= N4_ALL) return;
    const float4* src; __half* dst; long j = i;
    if (j < N4_A)            { src = wa; dst = oa; }
    else if ((j -= N4_A) < N4_P) { src = wp; dst = op; }
    else if ((j -= N4_P) < N4_F) { src = wf; dst = of; }
    else { j -= N4_F;          src = wm; dst = om; }
    float4 v = src[j];
    __half2* d2 = (__half2*)(dst + j * 4);
    d2[0] = __floats2half2_rn(v.x, v.y);
    d2[1] = __floats2half2_rn(v.z, v.w);
}

// ---------------------------------------------------------------------------
// LayerNorm: one block per row, 256 threads, 1 float4/thread; fp16 output.
__global__ void ln_kernel(const float* __restrict__ x,
                          const float* __restrict__ w,
                          const float* __restrict__ b,
                          __half* __restrict__ out)
{
    int row = blockIdx.x, tid = threadIdx.x;
    float4 v = ((const float4*)(x + (long)row * Cc))[tid];
    float s  = v.x + v.y + v.z + v.w;
    float s2 = v.x*v.x + v.y*v.y + v.z*v.z + v.w*v.w;
    __shared__ float rs[8], rs2[8];
    #pragma unroll
    for (int o = 16; o; o >>= 1) {
        s  += __shfl_xor_sync(0xffffffffu, s,  o);
        s2 += __shfl_xor_sync(0xffffffffu, s2, o);
    }
    int lane = tid & 31, wid = tid >> 5;
    if (lane == 0) { rs[wid] = s; rs2[wid] = s2; }
    __syncthreads();
    if (wid == 0) {
        s  = (lane < 8) ? rs[lane]  : 0.f;
        s2 = (lane < 8) ? rs2[lane] : 0.f;
        #pragma unroll
        for (int o = 4; o; o >>= 1) {
            s  += __shfl_xor_sync(0xffffffffu, s,  o);
            s2 += __shfl_xor_sync(0xffffffffu, s2, o);
        }
        if (lane == 0) { rs[0] = s; rs2[0] = s2; }
    }
    __syncthreads();
    float mean = rs[0] * (1.0f / Cc);
    float var  = rs2[0] * (1.0f / Cc) - mean * mean;
    float inv  = rsqrtf(var + 1e-5f);
    float4 w4 = ((const float4*)w)[tid];
    float4 b4 = ((const float4*)b)[tid];
    __half2* o2 = (__half2*)(out + (long)row * Cc + tid * 4);
    o2[0] = __floats2half2_rn((v.x - mean) * inv * w4.x + b4.x,
                              (v.y - mean) * inv * w4.y + b4.y);
    o2[1] = __floats2half2_rn((v.z - mean) * inv * w4.z + b4.z,
                              (v.w - mean) * inv * w4.w + b4.w);
}

// ---------------------------------------------------------------------------
// fp16 mma.sync GEMM (R16 body; EPI=0 now writes fp16 q/k/v).
template <int EPI>
__global__ __launch_bounds__(256, 2)
void gemm_f16_kernel(const __half* __restrict__ A,
                     const __half* __restrict__ W,
                     const float* __restrict__ bias,
                     const float* __restrict__ res,
                     float* __restrict__ outp,
                     __half* __restrict__ out_q,
                     __half* __restrict__ out_k,
                     __half* __restrict__ out_v,
                     float* __restrict__ pres_k,
                     float* __restrict__ pres_v,
                     int K, int N)
{
    extern __shared__ __half sh16[];
    __half* sA = sh16;
    __half* sB = sh16 + STG * ATILE16;
    uint32_t sAu = smem_u32(sA), sBu = smem_u32(sB);

    int tid = threadIdx.x;
    int mbase = blockIdx.y * 128, nbase = blockIdx.x * 128;
    int wid = tid >> 5, lane = tid & 31;
    int g = lane >> 2, tig = lane & 3;
    int wm = wid >> 2, wn = wid & 3;
    int moff = wm * 64, noff = wn * 32;
    int nst = K >> 6;

    float acc[4][4][4] = {};

    int aOff = (lane & 15) * TS16 + ((lane >> 4) << 3);
    int bOff = ((lane & 7) + ((lane >> 4) << 3)) * TS16 + (((lane >> 3) & 1) << 3);

    auto issueQ = [&](int st, int q) {
        if (st < nst) {
            int k0 = st << 6, buf = st % STG;
            int id = tid + (q << 8);
            int row = id >> 3, c8 = (id & 7) << 3;
            uint32_t off = ((buf * 128 + row) * TS16 + c8) * 2;
            cp_async16(sAu + off, A + (long)(mbase + row) * K + k0 + c8);
            cp_async16(sBu + off, W + (long)(nbase + row) * K + k0 + c8);
        }
    };
    auto issueAll = [&](int st) {
        #pragma unroll
        for (int q = 0; q < 4; q++) issueQ(st, q);
        CP_COMMIT();
    };

    issueAll(0);
    issueAll(1);

    for (int it = 0; it < nst; it++) {
        CP_WAIT1();
        __syncthreads();

        uint32_t cAu = sAu + ((it % STG) * ATILE16) * 2;
        uint32_t cBu = sBu + ((it % STG) * ATILE16) * 2;
        #pragma unroll
        for (int x = 0; x < 4; x++) {
            issueQ(it + 2, x);
            int kk = x * 16;
            unsigned afr[4][4], bfr[2][4];
            #pragma unroll
            for (int mf = 0; mf < 4; mf++)
                ldsm_x4(afr[mf],
                        cAu + (((moff + mf * 16) * TS16) + kk + aOff) * 2);
            #pragma unroll
            for (int np = 0; np < 2; np++)
                ldsm_x4(bfr[np],
                        cBu + (((noff + np * 16) * TS16) + kk + bOff) * 2);
            #pragma unroll
            for (int mf = 0; mf < 4; mf++) {
                #pragma unroll
                for (int nf = 0; nf < 4; nf++)
                    mma_f16(acc[mf][nf], afr[mf], bfr[nf >> 1] + ((nf & 1) << 1));
            }
        }
        CP_COMMIT();
    }

    if (EPI == 0) {
        int region = nbase >> 10;
        __half* dst  = (region == 0) ? out_q : (region == 1) ? out_k : out_v;
        float*  dst2 = (region == 1) ? pres_k : pres_v;
        #pragma unroll
        for (int mf = 0; mf < 4; mf++) {
            #pragma unroll
            for (int i = 0; i < 2; i++) {
                int row = mbase + moff + mf * 16 + g + i * 8;
                int bidx = row >> 11;
                int t    = row & (Tc - 1);
                #pragma unroll
                for (int nf = 0; nf < 4; nf++) {
                    int n = nbase + noff + nf * 8 + tig * 2;
                    float2 v;
                    v.x = acc[mf][nf][i * 2 + 0] + bias[n];
                    v.y = acc[mf][nf][i * 2 + 1] + bias[n + 1];
                    int nl = n & (Cc - 1);
                    int head = nl >> 6, d = nl & 63;
                    long idx = (((long)(bidx * Hc + head) * Tc) + t) * HDc + d;
                    if (region == 0) {
                        *(__half2*)(dst + idx) =
                            __floats2half2_rn(v.x * 0.125f, v.y * 0.125f);
                    } else {
                        *(__half2*)(dst + idx) = __floats2half2_rn(v.x, v.y);
                        dst2[idx] = v.x; dst2[idx + 1] = v.y;
                    }
                }
            }
        }
    } else {
        #pragma unroll
        for (int mf = 0; mf < 4; mf++) {
            #pragma unroll
            for (int i = 0; i < 2; i++) {
                int row = mbase + moff + mf * 16 + g + i * 8;
                #pragma unroll
                for (int nf = 0; nf < 4; nf++) {
                    int n = nbase + noff + nf * 8 + tig * 2;
                    long idx = (long)row * N + n;
                    float2 v;
                    v.x = acc[mf][nf][i * 2 + 0] + bias[n];
                    v.y = acc[mf][nf][i * 2 + 1] + bias[n + 1];
                    if (EPI == 1) {
                        float2 r2 = *(const float2*)(res + idx);
                        v.x += r2.x; v.y += r2.y;
                        *(float2*)(outp + idx) = v;
                    } else {
                        __half* o16 = reinterpret_cast<__half*>(outp);
                        *(__half2*)(o16 + idx) =
                            __floats2half2_rn(gelu_f(v.x), gelu_f(v.y));
                    }
                }
            }
        }
    }
}

// ---------------------------------------------------------------------------
// Flash attention, fp16 MMA: 64-row q-tile, 4 warps x 16 rows, m16n8k16.
// K double-buffered (P overlays current K), V via ldmatrix.trans, V-load
// hidden behind S+softmax, longest-first order. Y written as fp16.
__global__ __launch_bounds__(128, 3)
void flash_mma_kernel(const __half* __restrict__ Q,
                      const __half* __restrict__ Kp,
                      const __half* __restrict__ Vp,
                      __half* __restrict__ Y,
                      float* __restrict__ ent)
{
    extern __shared__ __half smh[];
    __half* Qs  = smh;                    // [64][QSh]
    __half* Ks0 = Qs  + 64 * QSh;         // [64][KSh] (P overlay)
    __half* Ks1 = Ks0 + 64 * KSh;         // [64][KSh] (P overlay)
    __half* Vs  = Ks1 + 64 * KSh;         // [64][VSh]
    float*  Hs  = (float*)(Vs + 64 * VSh);// [64]
    uint32_t Qsu  = smem_u32(Qs);
    uint32_t Ks0u = smem_u32(Ks0), Ks1u = smem_u32(Ks1);
    uint32_t Vsu  = smem_u32(Vs);

    int qt = (int)gridDim.x - 1 - blockIdx.x;   // longest first
    int h = blockIdx.y, b = blockIdx.z;
    int tid = threadIdx.x, wid = tid >> 5, lane = tid & 31;
    int g = lane >> 2, tig = lane & 3;
    int wrow = wid * 16;
    long bh = (long)(b * Hc + h);
    const __half* Qg = Q  + (bh * Tc + qt * 64) * HDc;
    const __half* Kg = Kp + bh * Tc * HDc;
    const __half* Vg = Vp + bh * Tc * HDc;

    // ldmatrix lane offsets (halves)
    int aOffQ = (lane & 15) * QSh + ((lane >> 4) << 3);
    int aOffP = (lane & 15) * KSh + ((lane >> 4) << 3);
    int bOffK = ((lane & 7) + ((lane >> 4) << 3)) * KSh + (((lane >> 3) & 1) << 3);
    // V trans frag: groups of 8 lanes -> matrices (k-lo,n-lo)(k-hi,n-lo)(k-lo,n-hi)(k-hi,n-hi)
    int vOff  = ((((lane >> 3) & 1) << 3) + (lane & 7)) * VSh + ((lane >> 4) << 3);

    // staging: 64 rows x 64 halves = 512 x 16B chunks -> 2 per thread per op
    int sr = tid >> 3, sc8 = (tid & 7) << 3;    // row 0..15, col-halves 0..56

    // prologue: stage Q and K(0) as ONE group
    {
        #pragma unroll
        for (int it = 0; it < 4; it++) {
            int row = sr + it * 16;
            cp_async16(Qsu  + (row * QSh + sc8) * 2, Qg + row * 64 + sc8);
            cp_async16(Ks0u + (row * KSh + sc8) * 2, Kg + row * 64 + sc8);
        }
        CP_COMMIT();
    }

    float m0 = -1e30f, m1 = -1e30f, l0 = 0.f, l1 = 0.f, ss0 = 0.f, ss1 = 0.f;
    float o_[8][4];
    #pragma unroll
    for (int i = 0; i < 8; i++)
        o_[i][0] = o_[i][1] = o_[i][2] = o_[i][3] = 0.f;

    int row_g0 = qt * 64 + wrow + g;
    int row_g1 = row_g0 + 8;

    for (int kt = 0; kt <= qt; kt++) {
        uint32_t Kbu = (kt & 1) ? Ks1u : Ks0u;
        __half*  Kb  = (kt & 1) ? Ks1  : Ks0;

        __syncthreads();          // prev PV readers done with all smem
        // issue V(kt)
        #pragma unroll
        for (int it = 0; it < 4; it++) {
            int row = sr + it * 16;
            cp_async16(Vsu + (row * VSh + sc8) * 2,
                       Vg + (kt * 64 + row) * 64 + sc8);
        }
        CP_COMMIT();

        CP_WAIT1();               // K(kt) complete
        __syncthreads();

        // ---- S = Q @ K^T (fp16, 4 k16-steps) ----
        float s[8][4];
        #pragma unroll
        for (int nf = 0; nf < 8; nf++)
            s[nf][0] = s[nf][1] = s[nf][2] = s[nf][3] = 0.f;

        #pragma unroll
        for (int ks = 0; ks < 4; ks++) {
            int kk = ks * 16;
            unsigned a[4];
            ldsm_x4(a, Qsu + (wrow * QSh + kk + aOffQ) * 2);
            unsigned bfr[4][4];
            #pragma unroll
            for (int np = 0; np < 4; np++)
                ldsm_x4(bfr[np], Kbu + ((np * 16) * KSh + kk + bOffK) * 2);
            #pragma unroll
            for (int nf = 0; nf < 8; nf++)
                mma_f16(s[nf], a, bfr[nf >> 1] + ((nf & 1) << 1));
        }

        __syncthreads();          // K(kt) fully read -> P overlay OK
        // issue K(kt+1) into the other buffer
        if (kt < qt) {
            uint32_t Knu = (kt & 1) ? Ks0u : Ks1u;
            #pragma unroll
            for (int it = 0; it < 4; it++) {
                int row = sr + it * 16;
                cp_async16(Knu + (row * KSh + sc8) * 2,
                           Kg + ((kt + 1) * 64 + row) * 64 + sc8);
            }
        }
        CP_COMMIT();

        // causal mask (diagonal tile only)
        if (kt == qt) {
            #pragma unroll
            for (int nf = 0; nf < 8; nf++) {
                int c = kt * 64 + nf * 8 + 2 * tig;
                if (c     > row_g0) s[nf][0] = -1e30f;
                if (c + 1 > row_g0) s[nf][1] = -1e30f;
                if (c     > row_g1) s[nf][2] = -1e30f;
                if (c + 1 > row_g1) s[nf][3] = -1e30f;
            }
        }

        float rm0 = -1e30f, rm1 = -1e30f;
        #pragma unroll
        for (int nf = 0; nf < 8; nf++) {
            rm0 = fmaxf(rm0, fmaxf(s[nf][0], s[nf][1]));
            rm1 = fmaxf(rm1, fmaxf(s[nf][2], s[nf][3]));
        }
        rm0 = fmaxf(rm0, __shfl_xor_sync(0xffffffffu, rm0, 1));
        rm0 = fmaxf(rm0, __shfl_xor_sync(0xffffffffu, rm0, 2));
        rm1 = fmaxf(rm1, __shfl_xor_sync(0xffffffffu, rm1, 1));
        rm1 = fmaxf(rm1, __shfl_xor_sync(0xffffffffu, rm1, 2));

        float mn0 = fmaxf(m0, rm0), mn1 = fmaxf(m1, rm1);
        float sc0 = fexp(m0 - mn0), sc1 = fexp(m1 - mn1);

        float rs0 = 0.f, rs1 = 0.f, rw0 = 0.f, rw1 = 0.f;
        __half* prow0 = Kb + (wrow + g) * KSh + 2 * tig;   // P overlays K(kt)
        __half* prow1 = prow0 + 8 * KSh;
        #pragma unroll
        for (int nf = 0; nf < 8; nf++) {
            float p00 = fexp(s[nf][0] - mn0), p01 = fexp(s[nf][1] - mn0);
            float p10 = fexp(s[nf][2] - mn1), p11 = fexp(s[nf][3] - mn1);
            rs0 += p00 + p01; rw0 += p00 * s[nf][0] + p01 * s[nf][1];
            rs1 += p10 + p11; rw1 += p10 * s[nf][2] + p11 * s[nf][3];
            *(__half2*)(prow0 + nf * 8) = __floats2half2_rn(p00, p01);
            *(__half2*)(prow1 + nf * 8) = __floats2half2_rn(p10, p11);
        }
        #pragma unroll
        for (int o = 1; o <= 2; o <<= 1) {
            rs0 += __shfl_xor_sync(0xffffffffu, rs0, o);
            rw0 += __shfl_xor_sync(0xffffffffu, rw0, o);
            rs1 += __shfl_xor_sync(0xffffffffu, rs1, o);
            rw1 += __shfl_xor_sync(0xffffffffu, rw1, o);
        }
        l0 = l0 * sc0 + rs0;  ss0 = ss0 * sc0 + rw0;  m0 = mn0;
        l1 = l1 * sc1 + rs1;  ss1 = ss1 * sc1 + rw1;  m1 = mn1;

        #pragma unroll
        for (int nf = 0; nf < 8; nf++) {
            o_[nf][0] *= sc0; o_[nf][1] *= sc0;
            o_[nf][2] *= sc1; o_[nf][3] *= sc1;
        }

        CP_WAIT1();               // V(kt) complete (K(kt+1) may be in flight)
        __syncthreads();          // V + P visible to all

        // ---- O += P @ V (P ldsm from K-overlay; V ldsm.trans) ----
        #pragma unroll
        for (int ks = 0; ks < 4; ks++) {
            int kk = ks * 16;
            unsigned a[4];
            ldsm_x4(a, Kbu + (wrow * KSh + kk + aOffP) * 2);
            #pragma unroll
            for (int vn = 0; vn < 4; vn++) {
                unsigned vfr[4];
                ldsm_x4_t(vfr, Vsu + (kk * VSh + vn * 16 + vOff) * 2);
                mma_f16(o_[vn * 2 + 0], a, vfr);
                mma_f16(o_[vn * 2 + 1], a, vfr + 2);
            }
        }
    }

    float li0 = 1.f / l0, li1 = 1.f / l1;
    int t0 = qt * 64 + wrow + g;
    __half* y0 = Y + ((long)(b * Tc + t0)) * Cc + h * 64 + 2 * tig;
    __half* y1 = y0 + 8 * Cc;
    #pragma unroll
    for (int nf = 0; nf < 8; nf++) {
        *(__half2*)(y0 + nf * 8) = __floats2half2_rn(o_[nf][0] * li0,
                                                     o_[nf][1] * li0);
        *(__half2*)(y1 + nf * 8) = __floats2half2_rn(o_[nf][2] * li1,
                                                     o_[nf][3] * li1);
    }

    if (tig == 0) {
        Hs[wrow + g]     = m0 + logf(l0) - ss0 / l0;
        Hs[wrow + g + 8] = m1 + logf(l1) - ss1 / l1;
    }
    __syncthreads();
    if (tid == 0) {
        float sum = 0.f;
        #pragma unroll 8
        for (int i = 0; i < 64; i++) sum += Hs[i];
        atomicAdd(ent, sum * (1.0f / (float)(Bc * Hc * Tc)));
    }
}

// ---------------------------------------------------------------------------
extern "C" void kernel_launch(void* const* d_in, const int* in_sizes, int n_in,
                              void* d_out, int out_size)
{
    const float* x      = (const float*)d_in[0];
    const float* ln1w   = (const float*)d_in[1];
    const float* ln1b   = (const float*)d_in[2];
    const float* w_attn = (const float*)d_in[3];
    const float* b_attn = (const float*)d_in[4];
    const float* w_proj = (const float*)d_in[5];
    const float* b_proj = (const float*)d_in[6];
    const float* ln2w   = (const float*)d_in[7];
    const float* ln2b   = (const float*)d_in[8];
    const float* w_fc   = (const float*)d_in[9];
    const float* b_fc   = (const float*)d_in[10];
    const float* w_mlp  = (const float*)d_in[11];
    const float* b_mlp  = (const float*)d_in[12];

    float* out   = (float*)d_out;
    float* x1    = out;            // x output region
    float* ent   = out + XS;       // scalar entropy
    float* presK = out + XS + 1;   // present[0] (unaligned -- scalar only)
    float* presV = presK + PRES;   // present[1]

    __half *ph, *pq, *pk, *pv, *pa, *pwa, *pwp, *pwf, *pwm;
    cudaGetSymbolAddress((void**)&ph,  g_h);
    cudaGetSymbolAddress((void**)&pq,  g_q);
    cudaGetSymbolAddress((void**)&pk,  g_k);
    cudaGetSymbolAddress((void**)&pv,  g_v);
    cudaGetSymbolAddress((void**)&pa,  g_a);
    cudaGetSymbolAddress((void**)&pwa, g_wa);
    cudaGetSymbolAddress((void**)&pwp, g_wp);
    cudaGetSymbolAddress((void**)&pwf, g_wf);
    cudaGetSymbolAddress((void**)&pwm, g_wm);

    cudaFuncSetAttribute(flash_mma_kernel,
                         cudaFuncAttributeMaxDynamicSharedMemorySize, FLASH_SMEM);
    cudaFuncSetAttribute(gemm_f16_kernel<0>,
                         cudaFuncAttributeMaxDynamicSharedMemorySize, GEMM_SMEM);
    cudaFuncSetAttribute(gemm_f16_kernel<1>,
                         cudaFuncAttributeMaxDynamicSharedMemorySize, GEMM_SMEM);
    cudaFuncSetAttribute(gemm_f16_kernel<2>,
                         cudaFuncAttributeMaxDynamicSharedMemorySize, GEMM_SMEM);

    // fused: zero entropy + fp16-convert all weights (one launch)
    cvt_all_kernel<<<(N4_ALL + 255) / 256, 256>>>(
        (const float4*)w_attn, (const float4*)w_proj,
        (const float4*)w_fc,   (const float4*)w_mlp,
        pwa, pwp, pwf, pwm, ent);

    // h = LN1(x)  (fp16 output)
    ln_kernel<<<Mrows, 256>>>(x, ln1w, ln1b, ph);

    // qkv = h @ w_attn^T + b_attn
    //   q (fp16,/8) -> g_q; k/v fp16 -> g_k/g_v; raw k/v -> present
    {
        dim3 g(3 * Cc / 128, Mrows / 128);
        gemm_f16_kernel<0><<<g, 256, GEMM_SMEM>>>(ph, pwa, b_attn, nullptr,
                                                  nullptr, pq, pk, pv,
                                                  presK, presV, Cc, 3 * Cc);
    }

    // flash attention: y -> g_h (fp16), entropy -> ent
    {
        dim3 g(Tc / 64, Hc, Bc);
        flash_mma_kernel<<<g, 128, FLASH_SMEM>>>(pq, pk, pv, ph, ent);
    }

    // x1 = x + y @ w_proj^T + b_proj
    {
        dim3 g(Cc / 128, Mrows / 128);
        gemm_f16_kernel<1><<<g, 256, GEMM_SMEM>>>(ph, pwp, b_proj, x,
                                                  x1, nullptr, nullptr, nullptr,
                                                  nullptr, nullptr, Cc, Cc);
    }

    // h2 = LN2(x1) -> g_h  (fp16)
    ln_kernel<<<Mrows, 256>>>(x1, ln2w, ln2b, ph);

    // a = gelu(h2 @ w_fc^T + b_fc) -> g_a  (fp16 in epilogue)
    {
        dim3 g(4 * Cc / 128, Mrows / 128);
        gemm_f16_kernel<2><<<g, 256, GEMM_SMEM>>>(ph, pwf, b_fc, nullptr,
                                                  (float*)pa, nullptr, nullptr, nullptr,
                                                  nullptr, nullptr, Cc, 4 * Cc);
    }

    // x_out = x1 + a @ w_mlp^T + b_mlp
    {
        dim3 g(Cc / 128, Mrows / 128);
        gemm_f16_kernel<1><<<g, 256, GEMM_SMEM>>>(pa, pwm, b_mlp, x1,
                                                  x1, nullptr, nullptr, nullptr,
                                                  nullptr, nullptr, 4 * Cc, Cc);
    }
}